// round 2
// baseline (speedup 1.0000x reference)
#include <cuda_runtime.h>

#define NBATCH 64
#define NCAT   128

__device__ __forceinline__ void ffma2(unsigned long long& d, unsigned long long a, unsigned long long b){
    asm("fma.rn.f32x2 %0, %1, %2, %0;" : "+l"(d) : "l"(a), "l"(b));
}
__device__ __forceinline__ float2 unpack2(unsigned long long v){
    float2 r;
    asm("mov.b64 {%0, %1}, %2;" : "=f"(r.x), "=f"(r.y) : "l"(v));
    return r;
}
__device__ __forceinline__ float tanh_acc(float x){
    float ax = fabsf(x);
    float e  = __expf(-2.0f * ax);
    float r  = __fdividef(1.0f - e, 1.0f + e);
    return copysignf(r, x);
}

// shared memory float offsets
#define OFF_W3 0        // [6][100][52]   = 31200
#define OFF_W2 31200    // [6][50][28]    =  8400
#define OFF_Y2 39600    // [25][64][2]    =  3200
#define OFF_Y1 42800    // [13][64][2]    =  1664
#define OFF_W1 44464    // [6][25]
#define OFF_B1 44614
#define OFF_B2 44764    // [6][50]
#define OFF_B3 45064    // [6][100]
#define OFF_T1 45664    // [64][12]
#define OFF_TY 46432    // [128] ints
#define SMEM_FLOATS 46560

__global__ __launch_bounds__(256, 1)
void feat_kernel(const float* __restrict__ coords, const int* __restrict__ atype,
                 const float* __restrict__ W1, const float* __restrict__ B1,
                 const float* __restrict__ W2, const float* __restrict__ B2,
                 const float* __restrict__ W3, const float* __restrict__ B3,
                 float* __restrict__ out)
{
    extern __shared__ float sm[];
    const int n   = blockIdx.x;
    const int tid = threadIdx.x;
    const int q   = tid >> 6;   // output quarter 0..3
    const int b   = tid & 63;   // batch lane

    float* w3s = sm + OFF_W3;
    float* w2s = sm + OFF_W2;
    float* y2s = sm + OFF_Y2;
    float* y1s = sm + OFF_Y1;
    float* w1s = sm + OFF_W1;
    float* b1s = sm + OFF_B1;
    float* b2s = sm + OFF_B2;
    float* b3s = sm + OFF_B3;
    float* t1s = sm + OFF_T1;
    int*   tys = (int*)(sm + OFF_TY);

    const int tc = atype[n];

    if (tid < NCAT) tys[tid] = atype[tid];
    // load 6 channels' weights for center type tc into smem (padded rows)
    for (int t = tid; t < 30000; t += 256){                 // W3: 6*100*50
        int c = t / 5000, r = t % 5000;
        int o = r / 50,   i = r % 50;
        w3s[c*5200 + o*52 + i] = W3[tc*30000 + t];
    }
    for (int t = tid; t < 1200; t += 256){                  // W3 pad -> 0
        int c = t / 200, r = t % 200;
        w3s[c*5200 + (r>>1)*52 + 50 + (r&1)] = 0.f;
    }
    for (int t = tid; t < 7500; t += 256){                  // W2: 6*50*25
        int c = t / 1250, r = t % 1250;
        int o = r / 25,   i = r % 25;
        w2s[c*1400 + o*28 + i] = W2[tc*7500 + t];
    }
    for (int t = tid; t < 900; t += 256){                   // W2 pad -> 0
        int c = t / 150, r = t % 150;
        w2s[c*1400 + (r/3)*28 + 25 + (r%3)] = 0.f;
    }
    for (int t = tid; t < 150; t += 256){
        w1s[t] = W1[tc*150 + t];
        b1s[t] = B1[tc*150 + t];
    }
    for (int t = tid; t < 300; t += 256) b2s[t] = B2[tc*300 + t];
    for (int t = tid; t < 600; t += 256) b3s[t] = B3[tc*600 + t];
    __syncthreads();

    const float cx = coords[(b*NCAT + n)*3 + 0];
    const float cy = coords[(b*NCAT + n)*3 + 1];
    const float cz = coords[(b*NCAT + n)*3 + 2];

    float M0[25], M1[25], M2[25];
    #pragma unroll
    for (int i = 0; i < 25; ++i){ M0[i]=0.f; M1[i]=0.f; M2[i]=0.f; }

    const int obase = q * 25;
    const int b2i   = b << 1;

    for (int k = 0; k < 127; ++k){
        const int j  = k + (k >= n);
        const int ch = tys[j];
        const float* cp = coords + (b*NCAT + j)*3;
        const float rx = cx - cp[0];
        const float ry = cy - cp[1];
        const float rz = cz - cp[2];
        const float d2   = fmaf(rx,rx, fmaf(ry,ry, rz*rz));
        const float dinv = rsqrtf(d2);
        const float dinv2 = dinv * dinv;
        const float a0 = rx*dinv2, a1 = ry*dinv2, a2 = rz*dinv2;

        // ---- layer 1: y1[i] = tanh(w1*dinv + b1), split across quarters ----
        {
            const float* w1c = w1s + ch*25;
            const float* b1c = b1s + ch*25;
            #pragma unroll
            for (int ii = 0; ii < 7; ++ii){
                int i = q + ii*4;
                if (i < 26){
                    float v = 0.f;
                    if (i < 25) v = tanh_acc(fmaf(w1c[i], dinv, b1c[i]));
                    y1s[(i>>1)*128 + b2i + (i&1)] = v;  // pair-packed [ip][b][2]
                }
            }
        }
        __syncthreads();

        // ---- layer 2: y2[o] = tanh(W2 y1 + b2) + y1[o%25] ----
        unsigned long long y1p[14];
        #pragma unroll
        for (int ip = 0; ip < 13; ++ip)
            y1p[ip] = *(const unsigned long long*)(y1s + ip*128 + b2i);
        y1p[13] = 0ull;
        {
            const float* w2c = w2s + ch*1400;
            const float* b2c = b2s + ch*50;
            #pragma unroll
            for (int t2 = 0; t2 < 13; ++t2){
                int o2 = q + t2*4;
                if (o2 < 50){
                    const float* row = w2c + o2*28;
                    unsigned long long accA = 0ull, accB = 0ull;
                    #pragma unroll
                    for (int v = 0; v < 7; ++v){
                        ulonglong2 w = *(const ulonglong2*)(row + v*4);
                        ffma2(accA, w.x, y1p[2*v]);
                        ffma2(accB, w.y, y1p[2*v+1]);
                    }
                    float2 la = unpack2(accA), lb = unpack2(accB);
                    float s = (la.x + la.y) + (lb.x + lb.y) + b2c[o2];
                    int m = o2 - (o2 >= 25 ? 25 : 0);
                    float resi = y1s[(m>>1)*128 + b2i + (m&1)];
                    y2s[(o2>>1)*128 + b2i + (o2&1)] = tanh_acc(s) + resi;
                }
            }
        }
        __syncthreads();

        // ---- layer 3 + M accumulation ----
        unsigned long long y2p[26];
        #pragma unroll
        for (int ip = 0; ip < 25; ++ip)
            y2p[ip] = *(const unsigned long long*)(y2s + ip*128 + b2i);
        y2p[25] = 0ull;
        {
            const float* w3c = w3s + ch*5200;
            const float* b3c = b3s + ch*100;
            const int mres = (q & 1) * 25;
            #pragma unroll
            for (int oi = 0; oi < 25; ++oi){
                const float* row = w3c + (obase + oi)*52;
                unsigned long long accA = 0ull, accB = 0ull;
                #pragma unroll
                for (int v = 0; v < 13; ++v){
                    ulonglong2 w = *(const ulonglong2*)(row + v*4);
                    ffma2(accA, w.x, y2p[2*v]);
                    ffma2(accB, w.y, y2p[2*v+1]);
                }
                float2 la = unpack2(accA), lb = unpack2(accB);
                float s = (la.x + la.y) + (lb.x + lb.y) + b3c[obase + oi];
                int m = mres + oi;
                float resi = y2s[(m>>1)*128 + b2i + (m&1)];
                float g = tanh_acc(s) + resi;
                M0[oi] = fmaf(a0, g, M0[oi]);
                M1[oi] = fmaf(a1, g, M1[oi]);
                M2[oi] = fmaf(a2, g, M2[oi]);
            }
        }
        __syncthreads();
    }

    // ---- finalize: res = M^T @ M[:, 0:4] ----
    if (q == 0){
        #pragma unroll
        for (int f = 0; f < 4; ++f){
            t1s[b*12 + f]     = M0[f];
            t1s[b*12 + 4 + f] = M1[f];
            t1s[b*12 + 8 + f] = M2[f];
        }
    }
    __syncthreads();
    float t10[4], t11[4], t12[4];
    #pragma unroll
    for (int f = 0; f < 4; ++f){
        t10[f] = t1s[b*12 + f];
        t11[f] = t1s[b*12 + 4 + f];
        t12[f] = t1s[b*12 + 8 + f];
    }
    float* op = out + (b*NCAT + n)*400 + obase*4;
    #pragma unroll
    for (int oi = 0; oi < 25; ++oi){
        float4 r;
        r.x = M0[oi]*t10[0] + M1[oi]*t11[0] + M2[oi]*t12[0];
        r.y = M0[oi]*t10[1] + M1[oi]*t11[1] + M2[oi]*t12[1];
        r.z = M0[oi]*t10[2] + M1[oi]*t11[2] + M2[oi]*t12[2];
        r.w = M0[oi]*t10[3] + M1[oi]*t11[3] + M2[oi]*t12[3];
        *(float4*)(op + oi*4) = r;
    }
}

extern "C" void kernel_launch(void* const* d_in, const int* in_sizes, int n_in,
                              void* d_out, int out_size)
{
    const float* coords = (const float*)d_in[0];
    const int*   atype  = (const int*)  d_in[1];
    const float* W1 = (const float*)d_in[2];
    const float* B1 = (const float*)d_in[3];
    const float* W2 = (const float*)d_in[4];
    const float* B2 = (const float*)d_in[5];
    const float* W3 = (const float*)d_in[6];
    const float* B3 = (const float*)d_in[7];
    float* out = (float*)d_out;

    const size_t smem = (size_t)SMEM_FLOATS * sizeof(float);
    cudaFuncSetAttribute(feat_kernel, cudaFuncAttributeMaxDynamicSharedMemorySize, (int)smem);
    feat_kernel<<<NCAT, 256, smem>>>(coords, atype, W1, B1, W2, B2, W3, B3, out);
}

// round 8
// speedup vs baseline: 1.3258x; 1.3258x over previous
#include <cuda_runtime.h>

#define NBATCH 64
#define NCAT   128
#define KC     16   // env staging chunk

__device__ __forceinline__ void ffma2(unsigned long long& d, unsigned long long a, unsigned long long b){
    asm("fma.rn.f32x2 %0, %1, %2, %0;" : "+l"(d) : "l"(a), "l"(b));
}
__device__ __forceinline__ float2 unpack2(unsigned long long v){
    float2 r;
    asm("mov.b64 {%0, %1}, %2;" : "=f"(r.x), "=f"(r.y) : "l"(v));
    return r;
}
__device__ __forceinline__ float tanha(float x){
    float y; asm("tanh.approx.f32 %0, %1;" : "=f"(y) : "f"(x)); return y;
}

// shared memory float offsets
#define OFF_W3  0        // [6][100][52] = 31200
#define OFF_W2  31200    // [6][50][28]  =  8400
#define OFF_Y1  39600    // 2 x [13][64][2] = 3328
#define OFF_Y2  42928    // 2 x [25][64][2] = 6400
#define OFF_ENV 49328    // [16][64][4]  = 4096
#define OFF_W1  53424    // 150
#define OFF_B1  53574    // 150
#define OFF_B2  53724    // 300
#define OFF_B3  54024    // 600
#define OFF_T1  54624    // 768
#define OFF_TY  55392    // 128
#define SMEM_FLOATS 55520

__global__ __launch_bounds__(512, 1)
void feat_kernel(const float* __restrict__ coords, const int* __restrict__ atype,
                 const float* __restrict__ W1, const float* __restrict__ B1,
                 const float* __restrict__ W2, const float* __restrict__ B2,
                 const float* __restrict__ W3, const float* __restrict__ B3,
                 float* __restrict__ out)
{
    extern __shared__ float sm[];
    const int n   = blockIdx.x;
    const int tid = threadIdx.x;
    const int q   = tid >> 6;   // 0..7
    const int b   = tid & 63;   // batch lane
    const int b2i = b << 1;

    float*  w3s = sm + OFF_W3;
    float*  w2s = sm + OFF_W2;
    float*  y1b = sm + OFF_Y1;
    float*  y2b = sm + OFF_Y2;
    float4* env = (float4*)(sm + OFF_ENV);
    float*  w1s = sm + OFF_W1;
    float*  b1s = sm + OFF_B1;
    float*  b2s = sm + OFF_B2;
    float*  b3s = sm + OFF_B3;
    float*  t1s = sm + OFF_T1;
    int*    tys = (int*)(sm + OFF_TY);

    const int tc = atype[n];

    if (tid < NCAT) tys[tid] = atype[tid];
    for (int t = tid; t < 30000; t += 512){                 // W3: 6*100*50
        int c = t / 5000, r = t % 5000;
        int o = r / 50,   i = r % 50;
        w3s[c*5200 + o*52 + i] = W3[tc*30000 + t];
    }
    for (int t = tid; t < 1200; t += 512){                  // W3 pad
        int c = t / 200, r = t % 200;
        w3s[c*5200 + (r>>1)*52 + 50 + (r&1)] = 0.f;
    }
    for (int t = tid; t < 7500; t += 512){                  // W2: 6*50*25
        int c = t / 1250, r = t % 1250;
        int o = r / 25,   i = r % 25;
        w2s[c*1400 + o*28 + i] = W2[tc*7500 + t];
    }
    for (int t = tid; t < 900; t += 512){                   // W2 pad
        int c = t / 150, r = t % 150;
        w2s[c*1400 + (r/3)*28 + 25 + (r%3)] = 0.f;
    }
    for (int t = tid; t < 150; t += 512){
        w1s[t] = W1[tc*150 + t];
        b1s[t] = B1[tc*150 + t];
    }
    for (int t = tid; t < 300; t += 512) b2s[t] = B2[tc*300 + t];
    for (int t = tid; t < 600; t += 512) b3s[t] = B3[tc*600 + t];
    __syncthreads();

    float M0[13], M1[13], M2[13];
    #pragma unroll
    for (int i = 0; i < 13; ++i){ M0[i]=0.f; M1[i]=0.f; M2[i]=0.f; }

    for (int k0 = 0; k0 < 127; k0 += KC){
        // ---- stage env for this chunk (semi-coalesced global reads) ----
        #pragma unroll
        for (int s = 0; s < 2; ++s){
            int p  = tid + s*512;
            int bb = p >> 4;
            int kk = p & 15;
            int k  = k0 + kk;
            if (k < 127){
                int j = k + (k >= n);
                const float* cc = coords + (bb*NCAT + n)*3;
                const float* cp = coords + (bb*NCAT + j)*3;
                float rx = cc[0] - cp[0];
                float ry = cc[1] - cp[1];
                float rz = cc[2] - cp[2];
                float d2   = fmaf(rx,rx, fmaf(ry,ry, rz*rz));
                float dinv = rsqrtf(d2);
                float di2  = dinv * dinv;
                env[kk*64 + bb] = make_float4(rx*di2, ry*di2, rz*di2, dinv);
            }
        }
        __syncthreads();

        const int kmax = (127 - k0 < KC) ? (127 - k0) : KC;
        for (int kk = 0; kk < kmax; ++kk){
            const int k = k0 + kk;
            const int j = k + (k >= n);
            const int ch = tys[j];
            const int p  = k & 1;
            float* y1s = y1b + p*1664;
            float* y2s = y2b + p*3200;

            float4 e = env[kk*64 + b];
            const float a0 = e.x, a1 = e.y, a2 = e.z, dinv = e.w;

            // ---- layer 1 ----
            {
                const float* w1c = w1s + ch*25;
                const float* b1c = b1s + ch*25;
                #pragma unroll
                for (int ii = 0; ii < 4; ++ii){
                    int i = q + ii*8;
                    if (i < 26){
                        float v = 0.f;
                        if (i < 25) v = tanha(fmaf(w1c[i], dinv, b1c[i]));
                        y1s[(i>>1)*128 + b2i + (i&1)] = v;
                    }
                }
            }
            __syncthreads();

            // ---- layer 2 ----
            unsigned long long y1p[14];
            #pragma unroll
            for (int ip = 0; ip < 13; ++ip)
                y1p[ip] = *(const unsigned long long*)(y1s + ip*128 + b2i);
            y1p[13] = 0ull;
            {
                const float* w2c = w2s + ch*1400;
                const float* b2c = b2s + ch*50;
                #pragma unroll
                for (int t2 = 0; t2 < 7; ++t2){
                    int o2 = q + t2*8;
                    if (o2 < 50){
                        const float* row = w2c + o2*28;
                        unsigned long long accA = 0ull, accB = 0ull;
                        #pragma unroll
                        for (int v = 0; v < 7; ++v){
                            ulonglong2 w = *(const ulonglong2*)(row + v*4);
                            ffma2(accA, w.x, y1p[2*v]);
                            ffma2(accB, w.y, y1p[2*v+1]);
                        }
                        float2 la = unpack2(accA), lb = unpack2(accB);
                        float s = (la.x + la.y) + (lb.x + lb.y) + b2c[o2];
                        int m = o2 - (o2 >= 25 ? 25 : 0);
                        float resi = y1s[(m>>1)*128 + b2i + (m&1)];
                        y2s[(o2>>1)*128 + b2i + (o2&1)] = tanha(s) + resi;
                    }
                }
            }
            __syncthreads();

            // ---- layer 3 + M accumulation ----
            unsigned long long y2p[26];
            #pragma unroll
            for (int ip = 0; ip < 25; ++ip)
                y2p[ip] = *(const unsigned long long*)(y2s + ip*128 + b2i);
            y2p[25] = 0ull;
            {
                const float* w3c = w3s + ch*5200;
                const float* b3c = b3s + ch*100;
                #pragma unroll
                for (int t = 0; t < 13; ++t){
                    int o = q + t*8;
                    if (o < 100){
                        const float* row = w3c + o*52;
                        unsigned long long accA = 0ull, accB = 0ull;
                        #pragma unroll
                        for (int v = 0; v < 13; ++v){
                            ulonglong2 w = *(const ulonglong2*)(row + v*4);
                            ffma2(accA, w.x, y2p[2*v]);
                            ffma2(accB, w.y, y2p[2*v+1]);
                        }
                        float2 la = unpack2(accA), lb = unpack2(accB);
                        float s = (la.x + la.y) + (lb.x + lb.y) + b3c[o];
                        int m = o - (o >= 50 ? 50 : 0);
                        float resi = y2s[(m>>1)*128 + b2i + (m&1)];
                        float g = tanha(s) + resi;
                        M0[t] = fmaf(a0, g, M0[t]);
                        M1[t] = fmaf(a1, g, M1[t]);
                        M2[t] = fmaf(a2, g, M2[t]);
                    }
                }
            }
            // no trailing barrier: y1/y2 double-buffered
        }
    }

    // ---- finalize: res[g][f] = sum_axis M[axis][g] * M[axis][f], f<4 ----
    __syncthreads();
    if (q < 4){   // rows o = q (t=0) are outputs 0..3
        t1s[b*12 + 0 + q] = M0[0];
        t1s[b*12 + 4 + q] = M1[0];
        t1s[b*12 + 8 + q] = M2[0];
    }
    __syncthreads();
    float t10[4], t11[4], t12[4];
    #pragma unroll
    for (int f = 0; f < 4; ++f){
        t10[f] = t1s[b*12 + f];
        t11[f] = t1s[b*12 + 4 + f];
        t12[f] = t1s[b*12 + 8 + f];
    }
    float* op = out + (b*NCAT + n)*400;
    #pragma unroll
    for (int t = 0; t < 13; ++t){
        int o = q + t*8;
        if (o < 100){
            float4 r;
            r.x = M0[t]*t10[0] + M1[t]*t11[0] + M2[t]*t12[0];
            r.y = M0[t]*t10[1] + M1[t]*t11[1] + M2[t]*t12[1];
            r.z = M0[t]*t10[2] + M1[t]*t11[2] + M2[t]*t12[2];
            r.w = M0[t]*t10[3] + M1[t]*t11[3] + M2[t]*t12[3];
            *(float4*)(op + o*4) = r;
        }
    }
}

extern "C" void kernel_launch(void* const* d_in, const int* in_sizes, int n_in,
                              void* d_out, int out_size)
{
    const float* coords = (const float*)d_in[0];
    const int*   atype  = (const int*)  d_in[1];
    const float* W1 = (const float*)d_in[2];
    const float* B1 = (const float*)d_in[3];
    const float* W2 = (const float*)d_in[4];
    const float* B2 = (const float*)d_in[5];
    const float* W3 = (const float*)d_in[6];
    const float* B3 = (const float*)d_in[7];
    float* out = (float*)d_out;

    const size_t smem = (size_t)SMEM_FLOATS * sizeof(float);
    cudaFuncSetAttribute(feat_kernel, cudaFuncAttributeMaxDynamicSharedMemorySize, (int)smem);
    feat_kernel<<<NCAT, 512, smem>>>(coords, atype, W1, B1, W2, B2, W3, B3, out);
}

// round 10
// speedup vs baseline: 1.5403x; 1.1618x over previous
#include <cuda_runtime.h>

#define NBATCH 64
#define NCAT   128
#define KC     16   // env staging chunk

__device__ __forceinline__ void ffma2(unsigned long long& d, unsigned long long a, unsigned long long b){
    asm("fma.rn.f32x2 %0, %1, %2, %0;" : "+l"(d) : "l"(a), "l"(b));
}
__device__ __forceinline__ float2 unpack2(unsigned long long v){
    float2 r;
    asm("mov.b64 {%0, %1}, %2;" : "=f"(r.x), "=f"(r.y) : "l"(v));
    return r;
}
__device__ __forceinline__ unsigned long long pack2(float lo, float hi){
    unsigned long long v;
    asm("mov.b64 %0, {%1, %2};" : "=l"(v) : "f"(lo), "f"(hi));
    return v;
}
__device__ __forceinline__ float tanha(float x){
    float y; asm("tanh.approx.f32 %0, %1;" : "=f"(y) : "f"(x)); return y;
}

// shared memory float offsets (same map as R8)
#define OFF_W3  0        // [6][100][52] = 31200
#define OFF_W2  31200    // [6][50][28]  =  8400
#define OFF_Y1  39600    // 2 x [13][64][2] = 3328
#define OFF_Y2  42928    // 2 x [25][64][2] = 6400
#define OFF_ENV 49328    // [16][64][4]  = 4096
#define OFF_W1  53424    // 150
#define OFF_B1  53574    // 150
#define OFF_B2  53724    // 300
#define OFF_B3  54024    // 600
#define OFF_T1  54624    // 768
#define OFF_TY  55392    // 128
#define SMEM_FLOATS 55520

__global__ __launch_bounds__(256, 1)
void feat_kernel(const float* __restrict__ coords, const int* __restrict__ atype,
                 const float* __restrict__ W1, const float* __restrict__ B1,
                 const float* __restrict__ W2, const float* __restrict__ B2,
                 const float* __restrict__ W3, const float* __restrict__ B3,
                 float* __restrict__ out)
{
    extern __shared__ float sm[];
    const int n    = blockIdx.x;
    const int tid  = threadIdx.x;
    const int q    = tid >> 5;        // 0..7
    const int lane = tid & 31;        // batch A = lane, batch B = lane+32
    const int bA2  = lane << 1;       // pair-packed offset batch A
    const int bB2  = (lane + 32) << 1;

    float*  w3s = sm + OFF_W3;
    float*  w2s = sm + OFF_W2;
    float*  y1b = sm + OFF_Y1;
    float*  y2b = sm + OFF_Y2;
    float4* env = (float4*)(sm + OFF_ENV);
    float*  w1s = sm + OFF_W1;
    float*  b1s = sm + OFF_B1;
    float*  b2s = sm + OFF_B2;
    float*  b3s = sm + OFF_B3;
    float*  t1s = sm + OFF_T1;
    int*    tys = (int*)(sm + OFF_TY);

    const int tc = atype[n];

    if (tid < NCAT) tys[tid] = atype[tid];
    for (int t = tid; t < 30000; t += 256){                 // W3: 6*100*50
        int c = t / 5000, r = t % 5000;
        int o = r / 50,   i = r % 50;
        w3s[c*5200 + o*52 + i] = W3[tc*30000 + t];
    }
    for (int t = tid; t < 1200; t += 256){                  // W3 pad
        int c = t / 200, r = t % 200;
        w3s[c*5200 + (r>>1)*52 + 50 + (r&1)] = 0.f;
    }
    for (int t = tid; t < 7500; t += 256){                  // W2: 6*50*25
        int c = t / 1250, r = t % 1250;
        int o = r / 25,   i = r % 25;
        w2s[c*1400 + o*28 + i] = W2[tc*7500 + t];
    }
    for (int t = tid; t < 900; t += 256){                   // W2 pad
        int c = t / 150, r = t % 150;
        w2s[c*1400 + (r/3)*28 + 25 + (r%3)] = 0.f;
    }
    for (int t = tid; t < 150; t += 256){
        w1s[t] = W1[tc*150 + t];
        b1s[t] = B1[tc*150 + t];
    }
    for (int t = tid; t < 300; t += 256) b2s[t] = B2[tc*300 + t];
    for (int t = tid; t < 600; t += 256) b3s[t] = B3[tc*600 + t];
    __syncthreads();

    // batch-packed M accumulators: 13 rows x 3 axes, each = (val_bA, val_bB)
    unsigned long long M0[13], M1[13], M2[13];
    #pragma unroll
    for (int i = 0; i < 13; ++i){ M0[i]=0ull; M1[i]=0ull; M2[i]=0ull; }

    for (int k0 = 0; k0 < 127; k0 += KC){
        // ---- stage env for this chunk ----
        #pragma unroll
        for (int s = 0; s < 4; ++s){
            int p  = tid + s*256;
            int bb = p >> 4;
            int kk = p & 15;
            int k  = k0 + kk;
            if (k < 127){
                int j = k + (k >= n);
                const float* cc = coords + (bb*NCAT + n)*3;
                const float* cp = coords + (bb*NCAT + j)*3;
                float rx = cc[0] - cp[0];
                float ry = cc[1] - cp[1];
                float rz = cc[2] - cp[2];
                float d2   = fmaf(rx,rx, fmaf(ry,ry, rz*rz));
                float dinv = rsqrtf(d2);
                float di2  = dinv * dinv;
                env[kk*64 + bb] = make_float4(rx*di2, ry*di2, rz*di2, dinv);
            }
        }
        __syncthreads();

        const int kmax = (127 - k0 < KC) ? (127 - k0) : KC;
        for (int kk = 0; kk < kmax; ++kk){
            const int k = k0 + kk;
            const int j = k + (k >= n);
            const int ch = tys[j];
            const int p  = k & 1;
            float* y1s = y1b + p*1664;
            float* y2s = y2b + p*3200;

            float4 eA = env[kk*64 + lane];
            float4 eB = env[kk*64 + lane + 32];
            const unsigned long long a0p = pack2(eA.x, eB.x);
            const unsigned long long a1p = pack2(eA.y, eB.y);
            const unsigned long long a2p = pack2(eA.z, eB.z);

            // ---- layer 1 (both batches) ----
            {
                const float* w1c = w1s + ch*25;
                const float* b1c = b1s + ch*25;
                #pragma unroll
                for (int ii = 0; ii < 4; ++ii){
                    int i = q + ii*8;
                    if (i < 26){
                        float vA = 0.f, vB = 0.f;
                        if (i < 25){
                            float w = w1c[i], bb1 = b1c[i];
                            vA = tanha(fmaf(w, eA.w, bb1));
                            vB = tanha(fmaf(w, eB.w, bb1));
                        }
                        y1s[(i>>1)*128 + bA2 + (i&1)] = vA;
                        y1s[(i>>1)*128 + bB2 + (i&1)] = vB;
                    }
                }
            }
            __syncthreads();

            // ---- layer 2 (both batches) ----
            unsigned long long y1pA[14], y1pB[14];
            #pragma unroll
            for (int ip = 0; ip < 13; ++ip){
                y1pA[ip] = *(const unsigned long long*)(y1s + ip*128 + bA2);
                y1pB[ip] = *(const unsigned long long*)(y1s + ip*128 + bB2);
            }
            y1pA[13] = 0ull; y1pB[13] = 0ull;
            {
                const float* w2c = w2s + ch*1400;
                const float* b2c = b2s + ch*50;
                #pragma unroll
                for (int t2 = 0; t2 < 7; ++t2){
                    int o2 = q + t2*8;
                    if (o2 < 50){
                        const float* row = w2c + o2*28;
                        unsigned long long aA1=0ull, aB1=0ull, aA2=0ull, aB2=0ull;
                        #pragma unroll
                        for (int v = 0; v < 7; ++v){
                            ulonglong2 w = *(const ulonglong2*)(row + v*4);
                            ffma2(aA1, w.x, y1pA[2*v]);
                            ffma2(aB1, w.y, y1pA[2*v+1]);
                            ffma2(aA2, w.x, y1pB[2*v]);
                            ffma2(aB2, w.y, y1pB[2*v+1]);
                        }
                        float bias = b2c[o2];
                        float2 lA1 = unpack2(aA1), lB1 = unpack2(aB1);
                        float2 lA2 = unpack2(aA2), lB2 = unpack2(aB2);
                        float sA = (lA1.x + lA1.y) + (lB1.x + lB1.y) + bias;
                        float sB = (lA2.x + lA2.y) + (lB2.x + lB2.y) + bias;
                        int m = o2 - (o2 >= 25 ? 25 : 0);
                        float resiA = y1s[(m>>1)*128 + bA2 + (m&1)];
                        float resiB = y1s[(m>>1)*128 + bB2 + (m&1)];
                        y2s[(o2>>1)*128 + bA2 + (o2&1)] = tanha(sA) + resiA;
                        y2s[(o2>>1)*128 + bB2 + (o2&1)] = tanha(sB) + resiB;
                    }
                }
            }
            __syncthreads();

            // ---- layer 3 + packed M accumulation ----
            unsigned long long y2pA[26], y2pB[26];
            #pragma unroll
            for (int ip = 0; ip < 25; ++ip){
                y2pA[ip] = *(const unsigned long long*)(y2s + ip*128 + bA2);
                y2pB[ip] = *(const unsigned long long*)(y2s + ip*128 + bB2);
            }
            y2pA[25] = 0ull; y2pB[25] = 0ull;
            {
                const float* w3c = w3s + ch*5200;
                const float* b3c = b3s + ch*100;
                #pragma unroll
                for (int t = 0; t < 13; ++t){
                    int o = q + t*8;
                    if (o < 100){
                        const float* row = w3c + o*52;
                        unsigned long long aA1=0ull, aB1=0ull, aA2=0ull, aB2=0ull;
                        #pragma unroll
                        for (int v = 0; v < 13; ++v){
                            ulonglong2 w = *(const ulonglong2*)(row + v*4);
                            ffma2(aA1, w.x, y2pA[2*v]);
                            ffma2(aB1, w.y, y2pA[2*v+1]);
                            ffma2(aA2, w.x, y2pB[2*v]);
                            ffma2(aB2, w.y, y2pB[2*v+1]);
                        }
                        float bias = b3c[o];
                        float2 lA1 = unpack2(aA1), lB1 = unpack2(aB1);
                        float2 lA2 = unpack2(aA2), lB2 = unpack2(aB2);
                        float sA = (lA1.x + lA1.y) + (lB1.x + lB1.y) + bias;
                        float sB = (lA2.x + lA2.y) + (lB2.x + lB2.y) + bias;
                        int m = o - (o >= 50 ? 50 : 0);
                        float resiA = y2s[(m>>1)*128 + bA2 + (m&1)];
                        float resiB = y2s[(m>>1)*128 + bB2 + (m&1)];
                        float gA = tanha(sA) + resiA;
                        float gB = tanha(sB) + resiB;
                        unsigned long long gp = pack2(gA, gB);
                        ffma2(M0[t], a0p, gp);
                        ffma2(M1[t], a1p, gp);
                        ffma2(M2[t], a2p, gp);
                    }
                }
            }
            // no trailing barrier: y1/y2 double-buffered
        }
    }

    // ---- finalize: res[g][f] = sum_axis M[axis][g] * M[axis][f], f<4 ----
    __syncthreads();
    if (q < 4){   // row o = q (t=0) holds outputs 0..3
        float2 m0 = unpack2(M0[0]);
        float2 m1 = unpack2(M1[0]);
        float2 m2 = unpack2(M2[0]);
        t1s[lane*12 + 0 + q] = m0.x;  t1s[(lane+32)*12 + 0 + q] = m0.y;
        t1s[lane*12 + 4 + q] = m1.x;  t1s[(lane+32)*12 + 4 + q] = m1.y;
        t1s[lane*12 + 8 + q] = m2.x;  t1s[(lane+32)*12 + 8 + q] = m2.y;
    }
    __syncthreads();
    float tA[12], tB[12];
    #pragma unroll
    for (int f = 0; f < 12; ++f){
        tA[f] = t1s[lane*12 + f];
        tB[f] = t1s[(lane+32)*12 + f];
    }
    float* opA = out + (lane*NCAT + n)*400;
    float* opB = out + ((lane+32)*NCAT + n)*400;
    #pragma unroll
    for (int t = 0; t < 13; ++t){
        int o = q + t*8;
        if (o < 100){
            float2 m0 = unpack2(M0[t]);
            float2 m1 = unpack2(M1[t]);
            float2 m2 = unpack2(M2[t]);
            float4 rA, rB;
            rA.x = m0.x*tA[0] + m1.x*tA[4] + m2.x*tA[8];
            rA.y = m0.x*tA[1] + m1.x*tA[5] + m2.x*tA[9];
            rA.z = m0.x*tA[2] + m1.x*tA[6] + m2.x*tA[10];
            rA.w = m0.x*tA[3] + m1.x*tA[7] + m2.x*tA[11];
            rB.x = m0.y*tB[0] + m1.y*tB[4] + m2.y*tB[8];
            rB.y = m0.y*tB[1] + m1.y*tB[5] + m2.y*tB[9];
            rB.z = m0.y*tB[2] + m1.y*tB[6] + m2.y*tB[10];
            rB.w = m0.y*tB[3] + m1.y*tB[7] + m2.y*tB[11];
            *(float4*)(opA + o*4) = rA;
            *(float4*)(opB + o*4) = rB;
        }
    }
}

extern "C" void kernel_launch(void* const* d_in, const int* in_sizes, int n_in,
                              void* d_out, int out_size)
{
    const float* coords = (const float*)d_in[0];
    const int*   atype  = (const int*)  d_in[1];
    const float* W1 = (const float*)d_in[2];
    const float* B1 = (const float*)d_in[3];
    const float* W2 = (const float*)d_in[4];
    const float* B2 = (const float*)d_in[5];
    const float* W3 = (const float*)d_in[6];
    const float* B3 = (const float*)d_in[7];
    float* out = (float*)d_out;

    const size_t smem = (size_t)SMEM_FLOATS * sizeof(float);
    cudaFuncSetAttribute(feat_kernel, cudaFuncAttributeMaxDynamicSharedMemorySize, (int)smem);
    feat_kernel<<<NCAT, 256, smem>>>(coords, atype, W1, B1, W2, B2, W3, B3, out);
}